// round 13
// baseline (speedup 1.0000x reference)
#include <cuda_runtime.h>
#include <cuda_bf16.h>
#include <stdint.h>

#define BSZ   64
#define TT    256
#define IND   64
#define HD    768
#define NB0   48          // layer0 CTAs (16 j-cols each)
#define NB1   96          // layer1 CTAs (8 j-cols each)
#define NCTAS (NB0 + NB1)
#define NTHR  256
#define STEP_WORDS 24576  // h frag buffer per step (48kt*4mt*32lane*4w = 98304 B)

// smem layout (bytes)
#define OFF_CS   106496   // after L0 B-frags (52kt*8nt*32*8B). L1 B is smaller (98304).
#define OFF_BIAS 139776   // OFF_CS + 2*16640
#define OFF_BASE 140288
#define SMEM_TOT 141568

__device__ __align__(16) unsigned g_Xf[(size_t)TT * 2048];         // x bf16 A-frags
__device__ __align__(16) unsigned g_H1f[(size_t)TT * STEP_WORDS];  // h1 frags, all t
__device__ __align__(16) unsigned g_H2f[2 * STEP_WORDS];           // h2 frags, parity
__device__ __align__(16) float    g_h2pl[BSZ * HD];                // planar fp32 h2 (last)
__device__ unsigned long long g_flag0[NB0 * 16];  // per-CTA step flags, 128B stride
__device__ unsigned long long g_flag1[NB1 * 16];

// ---------------------------------------------------------------------------
__device__ __forceinline__ unsigned long long ld_acq(const unsigned long long* p)
{
    unsigned long long v;
    asm volatile("ld.acquire.gpu.u64 %0, [%1];" : "=l"(v) : "l"(p) : "memory");
    return v;
}
__device__ __forceinline__ void st_rel(unsigned long long* p, unsigned long long v)
{
    asm volatile("st.release.gpu.u64 [%0], %1;" :: "l"(p), "l"(v) : "memory");
}
__device__ __forceinline__ float tanh_mufu(float x)
{
    float y;
    asm("tanh.approx.f32 %0, %1;" : "=f"(y) : "f"(x));
    return y;
}
__device__ __forceinline__ float sig_mufu(float x) { return 0.5f * tanh_mufu(0.5f * x) + 0.5f; }
__device__ __forceinline__ unsigned packbf(float lo, float hi)
{
    __nv_bfloat162 v = __floats2bfloat162_rn(lo, hi);
    return *reinterpret_cast<unsigned*>(&v);
}
__device__ __forceinline__ void mma16816(float* acc, uint4 a, uint2 b)
{
    asm volatile(
        "mma.sync.aligned.m16n8k16.row.col.f32.bf16.bf16.f32 "
        "{%0,%1,%2,%3}, {%4,%5,%6,%7}, {%8,%9}, {%0,%1,%2,%3};"
        : "+f"(acc[0]), "+f"(acc[1]), "+f"(acc[2]), "+f"(acc[3])
        : "r"(a.x), "r"(a.y), "r"(a.z), "r"(a.w), "r"(b.x), "r"(b.y));
}

template<int NTOT>
__device__ __forceinline__ void put_Bfrag(__nv_bfloat16* Bsh, int n, int k, float w)
{
    int kt = k >> 4, kr = k & 15, nt = n >> 3, nn = n & 7;
    int lane = nn * 4 + ((kr & 7) >> 1);
    int word = kr >> 3, half = kr & 1;
    Bsh[(((kt * NTOT + nt) * 32 + lane) * 2 + word) * 2 + half] = __float2bfloat16(w);
}

// Warp GEMM part: CNT k-tiles from A (local kt base akt0), B smem at kt bkt0.
// NT = nt tiles per warp (= NTOT, whole n-width). acc persists across parts.
template<int CNT, int NT>
__device__ __forceinline__ void gemm_part(const uint4* __restrict__ A, int akt0,
                                          const unsigned* __restrict__ Bs, int bkt0,
                                          float acc[2][NT][4], int lane, int mi)
{
    uint4 abuf[4][2];
    const int PD = (CNT < 4) ? CNT : 4;
#pragma unroll
    for (int i = 0; i < PD; i++) {
        abuf[i][0] = __ldcg(A + ((akt0 + i) * 4 + mi * 2 + 0) * 32 + lane);
        abuf[i][1] = __ldcg(A + ((akt0 + i) * 4 + mi * 2 + 1) * 32 + lane);
    }
#pragma unroll
    for (int kk = 0; kk < CNT; kk++) {
        uint4 a0 = abuf[kk & 3][0];
        uint4 a1 = abuf[kk & 3][1];
        if (kk + 4 < CNT) {
            abuf[kk & 3][0] = __ldcg(A + ((akt0 + kk + 4) * 4 + mi * 2 + 0) * 32 + lane);
            abuf[kk & 3][1] = __ldcg(A + ((akt0 + kk + 4) * 4 + mi * 2 + 1) * 32 + lane);
        }
        const unsigned* bb = Bs + (((bkt0 + kk) * NT) * 32 + lane) * 2;
#pragma unroll
        for (int nt = 0; nt < NT; nt++) {
            uint2 b2 = *(const uint2*)(bb + nt * 64);
            mma16816(acc[0][nt], a0, b2);
            mma16816(acc[1][nt], a1, b2);
        }
    }
}

// 2-slab dump: even ki assign, odd ki add. Caller syncs between phases.
template<int NT, int CST>
__device__ __forceinline__ void dump_slab(float acc[2][NT][4], float* Cs,
                                          int lane, int mi, bool add)
{
    const int gp = lane >> 2, tig = lane & 3;
#pragma unroll
    for (int am = 0; am < 2; am++)
#pragma unroll
        for (int nt = 0; nt < NT; nt++) {
            int row = mi * 32 + am * 16 + gp;
            int col = nt * 8 + tig * 2;
            float* c0 = Cs + row * CST + col;
            float* c1 = Cs + (row + 8) * CST + col;
            if (!add) {
                c0[0] = acc[am][nt][0];
                c0[1] = acc[am][nt][1];
                c1[0] = acc[am][nt][2];
                c1[1] = acc[am][nt][3];
            } else {
                c0[0] += acc[am][nt][0];
                c0[1] += acc[am][nt][1];
                c1[0] += acc[am][nt][2];
                c1[1] += acc[am][nt][3];
            }
        }
}

// ---------------------------------------------------------------------------
__global__ void xprep_kernel(const float* __restrict__ x)
{
    const int t = blockIdx.x;
    const int tid = threadIdx.x;
    const float inv = 1.0f / 1.5f;
    for (int idx = tid; idx < 512; idx += 256) {
        int lane = idx & 31;
        int fm = idx >> 5;
        int kt = fm >> 2, mt = fm & 3;
        int gp = lane >> 2, tig = lane & 3;
        int b0 = mt * 16 + gp, b1 = b0 + 8;
        int k0 = kt * 16 + tig * 2;
        const float* xb0 = x + ((size_t)b0 * TT + t) * IND;
        const float* xb1 = x + ((size_t)b1 * TT + t) * IND;
        uint4 v;
        v.x = packbf(xb0[k0] * inv,     xb0[k0 + 1] * inv);
        v.y = packbf(xb1[k0] * inv,     xb1[k0 + 1] * inv);
        v.z = packbf(xb0[k0 + 8] * inv, xb0[k0 + 9] * inv);
        v.w = packbf(xb1[k0 + 8] * inv, xb1[k0 + 9] * inv);
        ((uint4*)g_Xf)[t * 512 + idx] = v;
    }
}

// ---------------------------------------------------------------------------
// Fused decoupled recurrence, flag-array sync, waits overlapped with mma.
// CTAs 0..47   (L0): 16 j-cols, K=832 (x 4kt + h1 48kt).
// CTAs 48..143 (L1): 8 j-cols,  K=1536 (h1 48kt + h2 48kt).
// ---------------------------------------------------------------------------
__global__ void __launch_bounds__(NTHR, 1)
lstm_fused(const float* __restrict__ Wih0, const float* __restrict__ Whh0,
           const float* __restrict__ bih0, const float* __restrict__ bhh0,
           const float* __restrict__ Wih1, const float* __restrict__ Whh1,
           const float* __restrict__ bih1, const float* __restrict__ bhh1)
{
    extern __shared__ char smem[];
    unsigned*      Bs   = (unsigned*)smem;
    float*         CsA  = (float*)(smem + OFF_CS);
    float*         bsS  = (float*)(smem + OFF_BIAS);
    unsigned long long* bases = (unsigned long long*)(smem + OFF_BASE);  // [0..96) own, [96..144) L0
    __nv_bfloat16* Bsh  = (__nv_bfloat16*)smem;

    const int tid = threadIdx.x, lane = tid & 31, wid = tid >> 5;
    const int ki = wid >> 1, mi = wid & 1;
    const bool isB = (blockIdx.x >= NB0);

    // Launch bases (replay-safe: floor to multiple of 256; skew < 256 provable)
    if (!isB) {
        if (tid < NB0)
            bases[tid] = (ld_acq(&g_flag0[tid * 16]) / TT) * TT;
    } else {
        if (tid < NB1)
            bases[tid] = (ld_acq(&g_flag1[tid * 16]) / TT) * TT;
        if (tid >= 128 && tid < 128 + NB0)
            bases[96 + (tid - 128)] = (ld_acq(&g_flag0[(tid - 128) * 16]) / TT) * TT;
    }

    if (!isB) {
        // ----------------------------- LAYER 0 -----------------------------
        float* CsB = CsA + 4160;                     // 16640 B each, stride 65
        const int nb = blockIdx.x, j0 = nb * 16;

        for (int idx = tid; idx < 64 * 832; idx += NTHR) {
            int n = idx / 832, k = idx - n * 832;
            int gate = n >> 4, jj = n & 15;
            float w = (k < 64)
                ? Wih0[(size_t)(gate * 768 + j0 + jj) * 64 + k]
                : Whh0[(size_t)(gate * 768 + j0 + jj) * 768 + (k - 64)];
            put_Bfrag<8>(Bsh, n, k, w);
        }
        if (tid < 64) {
            int g = tid >> 4, jj = tid & 15;
            bsS[tid] = bih0[g * 768 + j0 + jj] + bhh0[g * 768 + j0 + jj];
        }
        __syncthreads();

        const int b = tid & 63, jg = tid >> 6;
        const int r = b & 15, mt = b >> 4;
        const int lane01 = (r & 7) * 4 + 2 * (jg & 1);
        const int reg01  = (r >> 3) + 2 * (jg >> 1);

        float cst[4] = {0.f, 0.f, 0.f, 0.f};

        for (int t = 0; t < TT; t++) {
            float acc[2][8][4];
#pragma unroll
            for (int am = 0; am < 2; am++)
#pragma unroll
                for (int nt = 0; nt < 8; nt++)
#pragma unroll
                    for (int e = 0; e < 4; e++) acc[am][nt][e] = 0.f;

            // x-part first (no dependency) — overlaps peers finishing t-1
            const uint4* srcX = (const uint4*)(g_Xf + (size_t)t * 2048);
            gemm_part<1, 8>(srcX, ki, Bs, ki, acc, lane, mi);

            if (t > 0) {
                // wait own group: peers published h1[t-1]
                if (tid < NB0) {
                    unsigned long long tgt = bases[tid] + (unsigned long long)t;
                    while (ld_acq(&g_flag0[tid * 16]) < tgt) { }
                }
                __syncthreads();
                const uint4* srcH = (const uint4*)(g_H1f + (size_t)(t - 1) * STEP_WORDS);
                gemm_part<12, 8>(srcH, ki * 12, Bs, 4 + ki * 12, acc, lane, mi);
            }

            float* slab = (ki < 2) ? CsA : CsB;
#pragma unroll
            for (int p = 0; p < 2; p++) {
                if ((ki & 1) == p)
                    dump_slab<8, 65>(acc, slab, lane, mi, p == 1);
                __syncthreads();
            }

            float h[4];
#pragma unroll
            for (int q = 0; q < 4; q++) {
                int c = jg * 4 + q;
                float gi = bsS[c]      + CsA[b * 65 + c]      + CsB[b * 65 + c];
                float gf = bsS[16 + c] + CsA[b * 65 + 16 + c] + CsB[b * 65 + 16 + c];
                float gg = bsS[32 + c] + CsA[b * 65 + 32 + c] + CsB[b * 65 + 32 + c];
                float go = bsS[48 + c] + CsA[b * 65 + 48 + c] + CsB[b * 65 + 48 + c];
                float I = sig_mufu(gi), F = sig_mufu(gf);
                float G = tanh_mufu(gg), O = sig_mufu(go);
                cst[q] = F * cst[q] + I * G;
                h[q] = O * tanh_mufu(cst[q]);
            }
            unsigned* dstp = g_H1f + (size_t)t * STEP_WORDS;
            dstp[((nb * 4 + mt) * 32 + lane01) * 4 + reg01]     = packbf(h[0], h[1]);
            dstp[((nb * 4 + mt) * 32 + lane01 + 1) * 4 + reg01] = packbf(h[2], h[3]);

            __syncthreads();
            if (tid == 0)
                st_rel(&g_flag0[nb * 16], bases[nb] + (unsigned long long)(t + 1));
        }
    } else {
        // ----------------------------- LAYER 1 -----------------------------
        float* CsB = CsA + 2112;                     // 8448 B each, stride 33
        const int s = blockIdx.x - NB0;              // 0..95
        const int jb = s * 8;
        const int ktF = s >> 1, shalf = s & 1;

        for (int idx = tid; idx < 32 * 1536; idx += NTHR) {
            int n = idx / 1536, k = idx - n * 1536;
            int gate = n >> 3, jj = n & 7;
            float w = (k < 768)
                ? Wih1[(size_t)(gate * 768 + jb + jj) * 768 + k]
                : Whh1[(size_t)(gate * 768 + jb + jj) * 768 + (k - 768)];
            put_Bfrag<4>(Bsh, n, k, w);
        }
        if (tid < 32) {
            int g = tid >> 3, jj = tid & 7;
            bsS[tid] = bih1[g * 768 + jb + jj] + bhh1[g * 768 + jb + jj];
        }
        __syncthreads();

        const int b = tid & 63, jp = tid >> 6;       // jp 0..3 -> cols jp*2, +1
        const int gpb = b & 7, hib = (b >> 3) & 1, mtb = b >> 4;
        const int wlane = gpb * 4 + jp;
        const int word  = hib + 2 * shalf;

        float cst[2] = {0.f, 0.f};

        for (int t = 0; t < TT; t++) {
            float acc[2][4][4];
#pragma unroll
            for (int am = 0; am < 2; am++)
#pragma unroll
                for (int nt = 0; nt < 4; nt++)
#pragma unroll
                    for (int e = 0; e < 4; e++) acc[am][nt][e] = 0.f;

            if (t > 0) {
                // own-group wait: peers published h2[t-1]
                if (tid < NB1) {
                    unsigned long long tgt = bases[tid] + (unsigned long long)t;
                    while (ld_acq(&g_flag1[tid * 16]) < tgt) { }
                }
                __syncthreads();
                const uint4* srcH2 = (const uint4*)(g_H2f + (size_t)((t - 1) & 1) * STEP_WORDS);
                gemm_part<12, 4>(srcH2, ki * 12, Bs, 48 + ki * 12, acc, lane, mi);
            }

            // wait L0: h1[t] published
            if (tid < NB0) {
                unsigned long long tgt = bases[96 + tid] + (unsigned long long)(t + 1);
                while (ld_acq(&g_flag0[tid * 16]) < tgt) { }
            }
            __syncthreads();
            const uint4* srcH1 = (const uint4*)(g_H1f + (size_t)t * STEP_WORDS);
            gemm_part<12, 4>(srcH1, ki * 12, Bs, ki * 12, acc, lane, mi);

            float* slab = (ki < 2) ? CsA : CsB;
#pragma unroll
            for (int p = 0; p < 2; p++) {
                if ((ki & 1) == p)
                    dump_slab<4, 33>(acc, slab, lane, mi, p == 1);
                __syncthreads();
            }

            float h[2];
#pragma unroll
            for (int q = 0; q < 2; q++) {
                int c = jp * 2 + q;
                float gi = bsS[c]      + CsA[b * 33 + c]      + CsB[b * 33 + c];
                float gf = bsS[8 + c]  + CsA[b * 33 + 8 + c]  + CsB[b * 33 + 8 + c];
                float gg = bsS[16 + c] + CsA[b * 33 + 16 + c] + CsB[b * 33 + 16 + c];
                float go = bsS[24 + c] + CsA[b * 33 + 24 + c] + CsB[b * 33 + 24 + c];
                float I = sig_mufu(gi), F = sig_mufu(gf);
                float G = tanh_mufu(gg), O = sig_mufu(go);
                cst[q] = F * cst[q] + I * G;
                h[q] = O * tanh_mufu(cst[q]);
            }
            g_H2f[((size_t)(t & 1) * STEP_WORDS)
                  + ((size_t)((ktF * 4 + mtb) * 32 + wlane) * 4 + word)] = packbf(h[0], h[1]);
            if (t == TT - 1) {
                float* hp = g_h2pl + (size_t)b * HD + jb + jp * 2;
                hp[0] = h[0]; hp[1] = h[1];
            }

            __syncthreads();
            if (tid == 0)
                st_rel(&g_flag1[s * 16], bases[s] + (unsigned long long)(t + 1));
        }
    }
}

// ---------------------------------------------------------------------------
// fc head, single kernel: block = batch, thread = LU unit.
// ---------------------------------------------------------------------------
__global__ void fc_kernel(const float* __restrict__ W1, const float* __restrict__ b1,
                          const float* __restrict__ W2, const float* __restrict__ b2,
                          float* __restrict__ out)
{
    const int b = blockIdx.x;
    const int l = threadIdx.x;

    __shared__ float hs[HD];
    for (int i = l; i < HD; i += 256)
        hs[i] = g_h2pl[(size_t)b * HD + i];
    __syncthreads();

    const float4* w1p = (const float4*)(W1 + (size_t)l * HD);
    const float4* hp4 = (const float4*)hs;
    float acc = 0.0f;
#pragma unroll 4
    for (int k4 = 0; k4 < 192; k4++) {
        float4 wv = w1p[k4];
        float4 hv = hp4[k4];
        acc += hv.x * wv.x + hv.y * wv.y + hv.z * wv.z + hv.w * wv.w;
    }
    float z = acc + b1[l];
    float p = (z / (1.0f + fabsf(z))) * W2[l];

    __shared__ float red[256];
    red[l] = p;
    __syncthreads();
    for (int off = 128; off > 0; off >>= 1) {
        if (l < off) red[l] += red[l + off];
        __syncthreads();
    }
    if (l == 0) out[b] = (red[0] + b2[0]) * 70.0f;
}

// ---------------------------------------------------------------------------
extern "C" void kernel_launch(void* const* d_in, const int* in_sizes, int n_in,
                              void* d_out, int out_size)
{
    const float* x    = (const float*)d_in[0];
    const float* Wih0 = (const float*)d_in[1];
    const float* Whh0 = (const float*)d_in[2];
    const float* bih0 = (const float*)d_in[3];
    const float* bhh0 = (const float*)d_in[4];
    const float* Wih1 = (const float*)d_in[5];
    const float* Whh1 = (const float*)d_in[6];
    const float* bih1 = (const float*)d_in[7];
    const float* bhh1 = (const float*)d_in[8];
    const float* W1   = (const float*)d_in[9];
    const float* b1   = (const float*)d_in[10];
    const float* W2   = (const float*)d_in[11];
    const float* b2   = (const float*)d_in[12];
    float* out = (float*)d_out;

    cudaFuncSetAttribute(lstm_fused, cudaFuncAttributeMaxDynamicSharedMemorySize, SMEM_TOT);

    xprep_kernel<<<TT, 256>>>(x);
    lstm_fused<<<NCTAS, NTHR, SMEM_TOT>>>(Wih0, Whh0, bih0, bhh0,
                                          Wih1, Whh1, bih1, bhh1);
    fc_kernel<<<BSZ, 256>>>(W1, b1, W2, b2, out);
}